// round 14
// baseline (speedup 1.0000x reference)
#include <cuda_runtime.h>
#include <cuda_fp16.h>
#include <stdint.h>
#include <math.h>

#define NVIEWS 26
#define CDIM   256
#define HW     1024
#define NSLOT  66
#define NHEAD  8
#define DHEAD  32
#define NBT    52   // 2 scenes * 26 views

// ---------------- scratch (static device globals; no allocation) ----------------
__device__ __half g_Xt  [(size_t)NBT     * HW * CDIM];   // fp16 [bt][s][c]
__device__ __half g_Wq16[(size_t)5 * 3 * 65536];         // fp16 w_qkv
__device__ __half g_Qh  [(size_t)NBT     * HW * CDIM];   // fp16 [bt][s][c], pre-scaled
__device__ __half g_Kh  [(size_t)2*NSLOT * HW * CDIM];   // fp16 [slot][key][c]
__device__ __half g_Vt  [(size_t)2*NSLOT * CDIM * HW];   // fp16 [slot][d][key]
__device__ float  g_AttO[(size_t)NBT     * HW * CDIM];   // fp32 [bt][s][c]

// ---------------- precomputed graph tables ----------------
__constant__ int c_mha[26] = {0,1,2,2,2,2,2,2,2,2,3,3,3,3,3,3,3,3,4,4,4,4,4,4,4,4};

__constant__ int c_pair_m[66] = {
  0,0,0,0, 1,1,1,1,
  2,2,2,2,2,2,2,2,2,2,2,2,2,2,2,2,2,
  3,3,3,3,3,3,3,3,3,3,3,3,3,3,3,3,3,3,3,3,3,3,3,3,
  4,4,4,4,4,4,4,4,4,4,4,4,4,4,4,4,4
};
__constant__ int c_pair_src[66] = {
  18,20,22,24, 2,4,6,8,
  1,2,3,4,5,6,7,8,9,10,11,12,13,14,15,16,17,
  2,3,4,5,6,7,8,9,10,11,12,13,14,15,16,17,18,19,20,21,22,23,24,25,
  0,10,11,12,13,14,15,16,17,18,19,20,21,22,23,24,25
};

__constant__ int c_selcnt[26] = {4,4, 4,3,4,3,4,3,4,3, 4,4,4,4,4,4,4,4, 4,3,4,3,4,3,4,3};
__constant__ int c_slots[26][4] = {
  { 0, 1, 2, 3}, { 4, 5, 6, 7},
  { 8,10,16,17}, { 9,11,18,-1}, { 8,10,12,19}, {11,13,20,-1},
  { 8,12,14,21}, {13,15,22,-1}, { 8,14,16,23}, { 9,15,24,-1},
  {25,34,40,41}, {26,33,35,42}, {27,34,36,43}, {28,35,37,44},
  {29,36,38,45}, {30,37,39,46}, {31,38,40,47}, {32,33,39,48},
  {49,50,59,65}, {51,58,60,-1}, {49,52,59,61}, {53,60,62,-1},
  {49,54,61,63}, {55,62,64,-1}, {49,56,63,65}, {57,58,64,-1}
};

// ---------------- PTX helpers (compute_103-safe; sm_80+ features only) ----------------
__device__ __forceinline__ float ex2f(float x) {
    float y; asm("ex2.approx.f32 %0,%1;" : "=f"(y) : "f"(x)); return y;
}
__device__ __forceinline__ void mma_fp16(float* d,
    uint32_t a0, uint32_t a1, uint32_t a2, uint32_t a3,
    uint32_t b0, uint32_t b1)
{
    asm volatile(
        "mma.sync.aligned.m16n8k16.row.col.f32.f16.f16.f32 "
        "{%0,%1,%2,%3},{%4,%5,%6,%7},{%8,%9},{%0,%1,%2,%3};"
        : "+f"(d[0]), "+f"(d[1]), "+f"(d[2]), "+f"(d[3])
        : "r"(a0), "r"(a1), "r"(a2), "r"(a3), "r"(b0), "r"(b1));
}
__device__ __forceinline__ uint32_t pack_h2(float lo, float hi) {
    __half2 h = __floats2half2_rn(lo, hi);
    return *(uint32_t*)&h;
}
__device__ __forceinline__ void f16_split(float x, __half& h, __half& l) {
    h = __float2half_rn(x);
    l = __float2half_rn(x - __half2float(h));
}

// =====================================================================
// Pre-pass A: transpose+convert x [bt][c][s] fp32 -> g_Xt [bt][s][c] fp16.
// Per-scene: grid (32, 8, 26)
// =====================================================================
__global__ __launch_bounds__(256) void xcvt_kernel(const float* __restrict__ x, int scene)
{
    __shared__ float t[32][33];
    const int bt = scene * NVIEWS + blockIdx.z;
    const int s0 = blockIdx.x * 32, c0 = blockIdx.y * 32;
    const int tx = threadIdx.x & 31, ty = threadIdx.x >> 5;
    const float* xb = x + (size_t)bt * CDIM * HW;
    #pragma unroll
    for (int j = 0; j < 4; j++)
        t[ty + j * 8][tx] = xb[(size_t)(c0 + ty + j * 8) * HW + s0 + tx];
    __syncthreads();
    __half* ob = g_Xt + (size_t)bt * HW * CDIM;
    #pragma unroll
    for (int j = 0; j < 4; j++)
        ob[(size_t)(s0 + ty + j * 8) * CDIM + c0 + tx] = __float2half_rn(t[tx][ty + j * 8]);
}

// =====================================================================
// Pre-pass B: convert w_qkv fp32 -> fp16.
// =====================================================================
__global__ __launch_bounds__(256) void wcvt_kernel(const float* __restrict__ w_qkv)
{
    int i = blockIdx.x * 256 + threadIdx.x;
    float4 v = ((const float4*)w_qkv)[i];
    uint2 o;
    o.x = pack_h2(v.x, v.y);
    o.y = pack_h2(v.z, v.w);
    ((uint2*)g_Wq16)[i] = o;
}

// =====================================================================
// Kernel 1: Q/K/V projections, pure-fp16 pipeline. Per-scene.
// grid: (8, 4, 158), block 256
// =====================================================================
__global__ __launch_bounds__(256) void proj_gemm_kernel(
    const float* __restrict__ b_qkv, int scene)
{
    __shared__ __half Xs[128][40];
    __shared__ __half Ws[64][40];

    const int job = blockIdx.z;
    const __half* Xsrc; const __half* W16; const float* bias; __half* Out;
    float osc = 1.f;
    int tmode = 0;
    if (job < NVIEWS) {
        int i = job, bt = scene * NVIEWS + i, m = c_mha[i];
        W16  = g_Wq16 + (size_t)m * 3 * 65536;
        bias = b_qkv + m * 768;
        Xsrc = g_Xt + (size_t)bt * HW * CDIM;
        Out  = g_Qh + (size_t)bt * HW * CDIM;
        osc  = 0.17677669529663687f * 1.4426950408889634f;   // 1/sqrt(32)*log2(e)
    } else {
        int r    = job - NVIEWS;
        int kv   = r / NSLOT;
        int slot = r % NSLOT;
        int m    = c_pair_m[slot], src = c_pair_src[slot];
        W16  = g_Wq16 + (size_t)m * 3 * 65536 + (size_t)(1 + kv) * 65536;
        bias = b_qkv + m * 768 + (1 + kv) * 256;
        Xsrc = g_Xt + (size_t)(scene * NVIEWS + src) * HW * CDIM;
        if (kv == 0) {
            Out = g_Kh + (size_t)(scene * NSLOT + slot) * HW * CDIM;
        } else {
            Out = g_Vt + (size_t)(scene * NSLOT + slot) * CDIM * HW;
            tmode = 1;
        }
    }

    const int m0  = blockIdx.x * 128;
    const int c0f = blockIdx.y * 64;
    const __half* A = Xsrc + (size_t)m0 * CDIM;
    const __half* W = W16 + (size_t)c0f * CDIM;

    const int tid  = threadIdx.x;
    const int lane = tid & 31, warp = tid >> 5;
    const int g4   = lane >> 2, c4 = lane & 3;
    const int wm   = warp >> 1, wn = warp & 1;
    const int mw   = wm * 32, nw = wn * 32;

    float acc[2][4][4];
    #pragma unroll
    for (int mt = 0; mt < 2; mt++)
        #pragma unroll
        for (int nt = 0; nt < 4; nt++)
            #pragma unroll
            for (int j = 0; j < 4; j++) acc[mt][nt][j] = 0.f;

    for (int k0 = 0; k0 < CDIM; k0 += 32) {
        __syncthreads();
        #pragma unroll
        for (int l = 0; l < 2; l++) {
            int idx = tid + l * 256;
            int ss = idx >> 2, kc = idx & 3;
            *(uint4*)&Xs[ss][kc * 8] =
                *(const uint4*)(A + (size_t)ss * CDIM + k0 + kc * 8);
        }
        {
            int nn = tid >> 2, kc = tid & 3;
            *(uint4*)&Ws[nn][kc * 8] =
                *(const uint4*)(W + (size_t)nn * CDIM + k0 + kc * 8);
        }
        __syncthreads();

        #pragma unroll
        for (int kt = 0; kt < 2; kt++) {
            const int kk = kt * 16;
            uint32_t ah[2][4];
            #pragma unroll
            for (int mt = 0; mt < 2; mt++) {
                int mloc = mw + mt * 16;
                ah[mt][0] = *(const uint32_t*)&Xs[mloc + g4    ][kk + 2 * c4    ];
                ah[mt][1] = *(const uint32_t*)&Xs[mloc + g4 + 8][kk + 2 * c4    ];
                ah[mt][2] = *(const uint32_t*)&Xs[mloc + g4    ][kk + 2 * c4 + 8];
                ah[mt][3] = *(const uint32_t*)&Xs[mloc + g4 + 8][kk + 2 * c4 + 8];
            }
            uint32_t bh[4][2];
            #pragma unroll
            for (int nt = 0; nt < 4; nt++) {
                int nrow = nw + nt * 8 + g4;
                bh[nt][0] = *(const uint32_t*)&Ws[nrow][kk + 2 * c4    ];
                bh[nt][1] = *(const uint32_t*)&Ws[nrow][kk + 2 * c4 + 8];
            }
            #pragma unroll
            for (int mt = 0; mt < 2; mt++)
                #pragma unroll
                for (int nt = 0; nt < 4; nt++)
                    mma_fp16(acc[mt][nt], ah[mt][0], ah[mt][1], ah[mt][2], ah[mt][3],
                             bh[nt][0], bh[nt][1]);
        }
    }

    #pragma unroll
    for (int mt = 0; mt < 2; mt++) {
        int r = m0 + mw + mt * 16 + g4;
        #pragma unroll
        for (int nt = 0; nt < 4; nt++) {
            int c = c0f + nw + nt * 8 + 2 * c4;
            float2 bb = *(const float2*)(bias + nw + nt * 8 + 2 * c4);
            if (tmode == 0) {
                uint32_t o0 = pack_h2((acc[mt][nt][0] + bb.x) * osc,
                                      (acc[mt][nt][1] + bb.y) * osc);
                uint32_t o1 = pack_h2((acc[mt][nt][2] + bb.x) * osc,
                                      (acc[mt][nt][3] + bb.y) * osc);
                *(uint32_t*)(Out + (size_t)r       * CDIM + c) = o0;
                *(uint32_t*)(Out + (size_t)(r + 8) * CDIM + c) = o1;
            } else {
                Out[(size_t)c       * HW + r    ] = __float2half_rn(acc[mt][nt][0] + bb.x);
                Out[(size_t)(c + 1) * HW + r    ] = __float2half_rn(acc[mt][nt][1] + bb.y);
                Out[(size_t)c       * HW + r + 8] = __float2half_rn(acc[mt][nt][2] + bb.x);
                Out[(size_t)(c + 1) * HW + r + 8] = __float2half_rn(acc[mt][nt][3] + bb.y);
            }
        }
    }
}

// =====================================================================
// Kernel 2: fp16 flash attention — 16 queries/warp, 8 warps = 128 q/CTA.
// Slim per-thread state (~70 regs) -> 3 CTAs/SM (launch_bounds-enforced),
// occ 37.5%: latency hiding via warps instead of fat ILP tiles.
// Interleaved exp->PV groups; register prefetch of next K/V tile.
// grid: (8, 8, 26), block 256
// =====================================================================
__global__ __launch_bounds__(256, 3) void attn_tc_kernel(int scene)
{
    __shared__ __half Ks[64][40];   // [key][d]
    __shared__ __half Vs[32][72];   // [d][key]

    const int tid  = threadIdx.x, lane = tid & 31, warp = tid >> 5;
    const int i    = blockIdx.z;
    const int b    = scene;
    const int bt   = scene * NVIEWS + i;
    const int h    = blockIdx.y;
    const int q0   = blockIdx.x * 128 + warp * 16;
    const int g4   = lane >> 2;
    const int c4   = lane & 3;

    // fill-role indices
    const int kr_row = tid >> 2, kr_q = tid & 3;   // K: 64 rows x 4 quads
    const int vr_d   = tid >> 3, vr_k = tid & 7;   // V: 32 rows x 8 quads

    // ---- Q fragments (16 rows) ----
    uint32_t qa[2][4];
    {
        const __half* Q = g_Qh + (size_t)bt * HW * CDIM + h * DHEAD;
        #pragma unroll
        for (int kt = 0; kt < 2; kt++) {
            int r = q0 + g4;
            int c = kt * 16 + 2 * c4;
            qa[kt][0] = *(const uint32_t*)(Q + (size_t)r       * CDIM + c);
            qa[kt][1] = *(const uint32_t*)(Q + (size_t)(r + 8) * CDIM + c);
            qa[kt][2] = *(const uint32_t*)(Q + (size_t)r       * CDIM + c + 8);
            qa[kt][3] = *(const uint32_t*)(Q + (size_t)(r + 8) * CDIM + c + 8);
        }
    }

    float O[4][4];
    #pragma unroll
    for (int nd = 0; nd < 4; nd++)
        #pragma unroll
        for (int j = 0; j < 4; j++) O[nd][j] = 0.f;
    float lsum[2] = {0.f, 0.f};   // rows g4 / g4+8

    const int cnt   = c_selcnt[i];
    const int total = cnt * 16;   // 64-key tiles

    // ---- prefetch tile 0 ----
    uint4 pk, pv;
    {
        int slot = c_slots[i][0];
        const __half* Kb = g_Kh + (size_t)(b * NSLOT + slot) * HW * CDIM + h * DHEAD;
        const __half* Vb = g_Vt + ((size_t)(b * NSLOT + slot) * CDIM + h * DHEAD) * HW;
        pk = *(const uint4*)(Kb + (size_t)kr_row * CDIM + kr_q * 8);
        pv = *(const uint4*)(Vb + (size_t)vr_d * HW + vr_k * 8);
    }

    for (int tile = 0; tile < total; tile++) {
        __syncthreads();
        *(uint4*)&Ks[kr_row][kr_q * 8] = pk;
        *(uint4*)&Vs[vr_d][vr_k * 8]   = pv;
        __syncthreads();

        if (tile + 1 < total) {
            int nslot = c_slots[i][(tile + 1) >> 4];
            int nt0   = ((tile + 1) & 15) * 64;
            const __half* Kb = g_Kh + (size_t)(b * NSLOT + nslot) * HW * CDIM + h * DHEAD;
            const __half* Vb = g_Vt + ((size_t)(b * NSLOT + nslot) * CDIM + h * DHEAD) * HW;
            pk = *(const uint4*)(Kb + (size_t)(nt0 + kr_row) * CDIM + kr_q * 8);
            pv = *(const uint4*)(Vb + (size_t)vr_d * HW + nt0 + vr_k * 8);
        }

        #pragma unroll
        for (int half = 0; half < 2; half++) {
            // ---- QK for keys [half*32, half*32+32) ----
            float sc[4][4];
            #pragma unroll
            for (int n4 = 0; n4 < 4; n4++)
                #pragma unroll
                for (int j = 0; j < 4; j++) sc[n4][j] = 0.f;

            #pragma unroll
            for (int n4 = 0; n4 < 4; n4++) {
                const __half* kr = &Ks[(half * 4 + n4) * 8 + g4][0];
                #pragma unroll
                for (int kt = 0; kt < 2; kt++) {
                    uint32_t b0 = *(const uint32_t*)(kr + kt * 16 + 2 * c4);
                    uint32_t b1 = *(const uint32_t*)(kr + kt * 16 + 2 * c4 + 8);
                    mma_fp16(sc[n4], qa[kt][0], qa[kt][1], qa[kt][2], qa[kt][3], b0, b1);
                }
            }

            // ---- per 16-key group: exp -> PV (MUFU overlaps tensor) ----
            #pragma unroll
            for (int g = 0; g < 2; g++) {
                const int ko = half * 32 + g * 16;
                float p00 = ex2f(sc[2*g][0]),   p01 = ex2f(sc[2*g][1]);
                float p02 = ex2f(sc[2*g][2]),   p03 = ex2f(sc[2*g][3]);
                float p10 = ex2f(sc[2*g+1][0]), p11 = ex2f(sc[2*g+1][1]);
                float p12 = ex2f(sc[2*g+1][2]), p13 = ex2f(sc[2*g+1][3]);
                lsum[0] += (p00 + p01) + (p10 + p11);
                lsum[1] += (p02 + p03) + (p12 + p13);
                uint32_t pa0 = pack_h2(p00, p01);
                uint32_t pa1 = pack_h2(p02, p03);
                uint32_t pa2 = pack_h2(p10, p11);
                uint32_t pa3 = pack_h2(p12, p13);
                #pragma unroll
                for (int nd = 0; nd < 4; nd++) {
                    const __half* vr = &Vs[nd * 8 + g4][0];
                    uint32_t b0 = *(const uint32_t*)(vr + ko + 2 * c4);
                    uint32_t b1 = *(const uint32_t*)(vr + ko + 2 * c4 + 8);
                    mma_fp16(O[nd], pa0, pa1, pa2, pa3, b0, b1);
                }
            }
        }
    }

    // ---- finalize ----
    #pragma unroll
    for (int j = 0; j < 2; j++) {
        lsum[j] += __shfl_xor_sync(0xffffffffu, lsum[j], 1);
        lsum[j] += __shfl_xor_sync(0xffffffffu, lsum[j], 2);
        lsum[j] = 1.f / lsum[j];
    }

    float* Ob = g_AttO + (size_t)bt * HW * CDIM + h * DHEAD;
    {
        int r = q0 + g4;
        #pragma unroll
        for (int nd = 0; nd < 4; nd++) {
            int col = nd * 8 + 2 * c4;
            float2 w0, w1;
            w0.x = O[nd][0] * lsum[0];
            w0.y = O[nd][1] * lsum[0];
            w1.x = O[nd][2] * lsum[1];
            w1.y = O[nd][3] * lsum[1];
            *(float2*)(Ob + (size_t)r       * CDIM + col) = w0;
            *(float2*)(Ob + (size_t)(r + 8) * CDIM + col) = w1;
        }
    }
}

// =====================================================================
// Kernel 3: output projection via split-fp16 MMA (3 products). Per-scene.
// grid: (8, 4, 26), block 256
// =====================================================================
struct SmemOut {
    __half Xh[128][40];
    __half Wh[64][40];
    __half Xl[128][40];
    __half Wl[64][40];
};

__global__ __launch_bounds__(256) void outproj_kernel(
    const float* __restrict__ w_out,
    const float* __restrict__ b_out,
    float* __restrict__ out, int scene)
{
    __shared__ SmemOut S;
    const int i  = blockIdx.z;
    const int bt = scene * NVIEWS + i;
    const int m  = c_mha[i];
    const float* W    = w_out + (size_t)m * 65536 + (size_t)(blockIdx.y * 64) * CDIM;
    const float* bias = b_out + m * 256 + blockIdx.y * 64;
    const float* A    = g_AttO + (size_t)bt * HW * CDIM + (size_t)(blockIdx.x * 128) * CDIM;
    float*       Op   = out + (size_t)bt * CDIM * HW;

    const int m0  = blockIdx.x * 128;
    const int c0f = blockIdx.y * 64;

    const int tid  = threadIdx.x;
    const int lane = tid & 31, warp = tid >> 5;
    const int g4   = lane >> 2, c4 = lane & 3;
    const int wm   = warp >> 1, wn = warp & 1;
    const int mw   = wm * 32, nw = wn * 32;

    float acc[2][4][4];
    #pragma unroll
    for (int mt = 0; mt < 2; mt++)
        #pragma unroll
        for (int nt = 0; nt < 4; nt++)
            #pragma unroll
            for (int j = 0; j < 4; j++) acc[mt][nt][j] = 0.f;

    for (int k0 = 0; k0 < CDIM; k0 += 32) {
        __syncthreads();
        #pragma unroll
        for (int l = 0; l < 4; l++) {
            int idx = tid + l * 256;
            int ss = idx >> 3, kc = idx & 7;
            float4 v = *(const float4*)(A + (size_t)ss * CDIM + k0 + kc * 4);
            __half h0,l0,h1,l1,h2,l2,h3,l3;
            f16_split(v.x, h0, l0); f16_split(v.y, h1, l1);
            f16_split(v.z, h2, l2); f16_split(v.w, h3, l3);
            __half2 ha; ha.x = h0; ha.y = h1;
            __half2 hb; hb.x = h2; hb.y = h3;
            __half2 la; la.x = l0; la.y = l1;
            __half2 lb; lb.x = l2; lb.y = l3;
            *(__half2*)&S.Xh[ss][kc * 4]     = ha;
            *(__half2*)&S.Xh[ss][kc * 4 + 2] = hb;
            *(__half2*)&S.Xl[ss][kc * 4]     = la;
            *(__half2*)&S.Xl[ss][kc * 4 + 2] = lb;
        }
        #pragma unroll
        for (int l = 0; l < 2; l++) {
            int idx = tid + l * 256;
            int nn = idx >> 3, kc = idx & 7;
            float4 v = *(const float4*)(W + (size_t)nn * CDIM + k0 + kc * 4);
            __half h0,l0,h1,l1,h2,l2,h3,l3;
            f16_split(v.x, h0, l0); f16_split(v.y, h1, l1);
            f16_split(v.z, h2, l2); f16_split(v.w, h3, l3);
            __half2 ha; ha.x = h0; ha.y = h1;
            __half2 hb; hb.x = h2; hb.y = h3;
            __half2 la; la.x = l0; la.y = l1;
            __half2 lb; lb.x = l2; lb.y = l3;
            *(__half2*)&S.Wh[nn][kc * 4]     = ha;
            *(__half2*)&S.Wh[nn][kc * 4 + 2] = hb;
            *(__half2*)&S.Wl[nn][kc * 4]     = la;
            *(__half2*)&S.Wl[nn][kc * 4 + 2] = lb;
        }
        __syncthreads();

        #pragma unroll
        for (int kt = 0; kt < 2; kt++) {
            const int kk = kt * 16;
            uint32_t ah[2][4], al[2][4];
            #pragma unroll
            for (int mt = 0; mt < 2; mt++) {
                int mloc = mw + mt * 16;
                ah[mt][0] = *(const uint32_t*)&S.Xh[mloc + g4    ][kk + 2 * c4    ];
                ah[mt][1] = *(const uint32_t*)&S.Xh[mloc + g4 + 8][kk + 2 * c4    ];
                ah[mt][2] = *(const uint32_t*)&S.Xh[mloc + g4    ][kk + 2 * c4 + 8];
                ah[mt][3] = *(const uint32_t*)&S.Xh[mloc + g4 + 8][kk + 2 * c4 + 8];
                al[mt][0] = *(const uint32_t*)&S.Xl[mloc + g4    ][kk + 2 * c4    ];
                al[mt][1] = *(const uint32_t*)&S.Xl[mloc + g4 + 8][kk + 2 * c4    ];
                al[mt][2] = *(const uint32_t*)&S.Xl[mloc + g4    ][kk + 2 * c4 + 8];
                al[mt][3] = *(const uint32_t*)&S.Xl[mloc + g4 + 8][kk + 2 * c4 + 8];
            }
            uint32_t bh[4][2], bl[4][2];
            #pragma unroll
            for (int nt = 0; nt < 4; nt++) {
                int nrow = nw + nt * 8 + g4;
                bh[nt][0] = *(const uint32_t*)&S.Wh[nrow][kk + 2 * c4    ];
                bh[nt][1] = *(const uint32_t*)&S.Wh[nrow][kk + 2 * c4 + 8];
                bl[nt][0] = *(const uint32_t*)&S.Wl[nrow][kk + 2 * c4    ];
                bl[nt][1] = *(const uint32_t*)&S.Wl[nrow][kk + 2 * c4 + 8];
            }
            #pragma unroll
            for (int mt = 0; mt < 2; mt++)
                #pragma unroll
                for (int nt = 0; nt < 4; nt++) {
                    mma_fp16(acc[mt][nt], ah[mt][0], ah[mt][1], ah[mt][2], ah[mt][3],
                             bh[nt][0], bh[nt][1]);
                    mma_fp16(acc[mt][nt], al[mt][0], al[mt][1], al[mt][2], al[mt][3],
                             bh[nt][0], bh[nt][1]);
                    mma_fp16(acc[mt][nt], ah[mt][0], ah[mt][1], ah[mt][2], ah[mt][3],
                             bl[nt][0], bl[nt][1]);
                }
        }
    }

    #pragma unroll
    for (int mt = 0; mt < 2; mt++) {
        int r = m0 + mw + mt * 16 + g4;
        #pragma unroll
        for (int nt = 0; nt < 4; nt++) {
            int c = c0f + nw + nt * 8 + 2 * c4;
            float2 bb = *(const float2*)(bias + nw + nt * 8 + 2 * c4);
            Op[(size_t)c       * HW + r    ] = acc[mt][nt][0] + bb.x;
            Op[(size_t)(c + 1) * HW + r    ] = acc[mt][nt][1] + bb.y;
            Op[(size_t)c       * HW + r + 8] = acc[mt][nt][2] + bb.x;
            Op[(size_t)(c + 1) * HW + r + 8] = acc[mt][nt][3] + bb.y;
        }
    }
}

// =====================================================================
// Launcher: two-scene fork/join on non-blocking streams (committed R12).
// =====================================================================
extern "C" void kernel_launch(void* const* d_in, const int* in_sizes, int n_in,
                              void* d_out, int out_size)
{
    const float* x     = (const float*)d_in[0];
    const float* w_qkv = (const float*)d_in[1];
    const float* b_qkv = (const float*)d_in[2];
    const float* w_out = (const float*)d_in[3];
    const float* b_out = (const float*)d_in[4];
    float* out = (float*)d_out;

    cudaStream_t sA, sB;
    cudaStreamCreateWithFlags(&sA, cudaStreamNonBlocking);
    cudaStreamCreateWithFlags(&sB, cudaStreamNonBlocking);
    cudaEvent_t eFork, eW, eA, eB;
    cudaEventCreateWithFlags(&eFork, cudaEventDisableTiming);
    cudaEventCreateWithFlags(&eW,    cudaEventDisableTiming);
    cudaEventCreateWithFlags(&eA,    cudaEventDisableTiming);
    cudaEventCreateWithFlags(&eB,    cudaEventDisableTiming);

    cudaEventRecord(eFork, 0);
    cudaStreamWaitEvent(sA, eFork, 0);
    cudaStreamWaitEvent(sB, eFork, 0);

    dim3 gx(HW / 32, CDIM / 32, NVIEWS);               // (32, 8, 26)
    dim3 g1(HW / 128, CDIM / 64, NVIEWS + 2 * NSLOT);  // (8, 4, 158)
    dim3 g2(HW / 128, NHEAD, NVIEWS);                  // (8, 8, 26)
    dim3 g3(HW / 128, CDIM / 64, NVIEWS);              // (8, 4, 26)

    wcvt_kernel<<<960, 256, 0, sA>>>(w_qkv);
    cudaEventRecord(eW, sA);
    xcvt_kernel<<<gx, 256, 0, sA>>>(x, 0);
    proj_gemm_kernel<<<g1, 256, 0, sA>>>(b_qkv, 0);
    attn_tc_kernel<<<g2, 256, 0, sA>>>(0);
    outproj_kernel<<<g3, 256, 0, sA>>>(w_out, b_out, out, 0);

    xcvt_kernel<<<gx, 256, 0, sB>>>(x, 1);
    cudaStreamWaitEvent(sB, eW, 0);
    proj_gemm_kernel<<<g1, 256, 0, sB>>>(b_qkv, 1);
    attn_tc_kernel<<<g2, 256, 0, sB>>>(1);
    outproj_kernel<<<g3, 256, 0, sB>>>(w_out, b_out, out, 1);

    cudaEventRecord(eA, sA);
    cudaEventRecord(eB, sB);
    cudaStreamWaitEvent(0, eA, 0);
    cudaStreamWaitEvent(0, eB, 0);

    cudaEventDestroy(eFork);
    cudaEventDestroy(eW);
    cudaEventDestroy(eA);
    cudaEventDestroy(eB);
    cudaStreamDestroy(sA);
    cudaStreamDestroy(sB);
}

// round 15
// speedup vs baseline: 1.0805x; 1.0805x over previous
#include <cuda_runtime.h>
#include <cuda_fp16.h>
#include <stdint.h>
#include <math.h>

#define NVIEWS 26
#define CDIM   256
#define HW     1024
#define NSLOT  66
#define NHEAD  8
#define DHEAD  32
#define NBT    52   // 2 scenes * 26 views

// ---------------- scratch (static device globals; no allocation) ----------------
__device__ __half g_Xt  [(size_t)NBT     * HW * CDIM];   // fp16 [bt][s][c]
__device__ __half g_Wq16[(size_t)5 * 3 * 65536];         // fp16 w_qkv
__device__ __half g_Qh  [(size_t)NBT     * HW * CDIM];   // fp16 [bt][s][c], pre-scaled
__device__ __half g_Kh  [(size_t)2*NSLOT * HW * CDIM];   // fp16 [slot][key][c]
__device__ __half g_Vt  [(size_t)2*NSLOT * CDIM * HW];   // fp16 [slot][d][key]
__device__ float  g_AttO[(size_t)NBT     * HW * CDIM];   // fp32 [bt][s][c]

// ---------------- precomputed graph tables ----------------
__constant__ int c_mha[26] = {0,1,2,2,2,2,2,2,2,2,3,3,3,3,3,3,3,3,4,4,4,4,4,4,4,4};

__constant__ int c_pair_m[66] = {
  0,0,0,0, 1,1,1,1,
  2,2,2,2,2,2,2,2,2,2,2,2,2,2,2,2,2,
  3,3,3,3,3,3,3,3,3,3,3,3,3,3,3,3,3,3,3,3,3,3,3,3,
  4,4,4,4,4,4,4,4,4,4,4,4,4,4,4,4,4
};
__constant__ int c_pair_src[66] = {
  18,20,22,24, 2,4,6,8,
  1,2,3,4,5,6,7,8,9,10,11,12,13,14,15,16,17,
  2,3,4,5,6,7,8,9,10,11,12,13,14,15,16,17,18,19,20,21,22,23,24,25,
  0,10,11,12,13,14,15,16,17,18,19,20,21,22,23,24,25
};

__constant__ int c_selcnt[26] = {4,4, 4,3,4,3,4,3,4,3, 4,4,4,4,4,4,4,4, 4,3,4,3,4,3,4,3};
__constant__ int c_slots[26][4] = {
  { 0, 1, 2, 3}, { 4, 5, 6, 7},
  { 8,10,16,17}, { 9,11,18,-1}, { 8,10,12,19}, {11,13,20,-1},
  { 8,12,14,21}, {13,15,22,-1}, { 8,14,16,23}, { 9,15,24,-1},
  {25,34,40,41}, {26,33,35,42}, {27,34,36,43}, {28,35,37,44},
  {29,36,38,45}, {30,37,39,46}, {31,38,40,47}, {32,33,39,48},
  {49,50,59,65}, {51,58,60,-1}, {49,52,59,61}, {53,60,62,-1},
  {49,54,61,63}, {55,62,64,-1}, {49,56,63,65}, {57,58,64,-1}
};

// ---------------- PTX helpers (compute_103-safe; sm_80+ features only) ----------------
__device__ __forceinline__ float ex2f(float x) {
    float y; asm("ex2.approx.f32 %0,%1;" : "=f"(y) : "f"(x)); return y;
}
__device__ __forceinline__ void mma_fp16(float* d,
    uint32_t a0, uint32_t a1, uint32_t a2, uint32_t a3,
    uint32_t b0, uint32_t b1)
{
    asm volatile(
        "mma.sync.aligned.m16n8k16.row.col.f32.f16.f16.f32 "
        "{%0,%1,%2,%3},{%4,%5,%6,%7},{%8,%9},{%0,%1,%2,%3};"
        : "+f"(d[0]), "+f"(d[1]), "+f"(d[2]), "+f"(d[3])
        : "r"(a0), "r"(a1), "r"(a2), "r"(a3), "r"(b0), "r"(b1));
}
__device__ __forceinline__ uint32_t pack_h2(float lo, float hi) {
    __half2 h = __floats2half2_rn(lo, hi);
    return *(uint32_t*)&h;
}
__device__ __forceinline__ void f16_split(float x, __half& h, __half& l) {
    h = __float2half_rn(x);
    l = __float2half_rn(x - __half2float(h));
}

// =====================================================================
// Pre-pass A: transpose+convert x [bt][c][s] fp32 -> g_Xt [bt][s][c] fp16.
// Per-scene: grid (32, 8, 26)
// =====================================================================
__global__ __launch_bounds__(256) void xcvt_kernel(const float* __restrict__ x, int scene)
{
    __shared__ float t[32][33];
    const int bt = scene * NVIEWS + blockIdx.z;
    const int s0 = blockIdx.x * 32, c0 = blockIdx.y * 32;
    const int tx = threadIdx.x & 31, ty = threadIdx.x >> 5;
    const float* xb = x + (size_t)bt * CDIM * HW;
    #pragma unroll
    for (int j = 0; j < 4; j++)
        t[ty + j * 8][tx] = xb[(size_t)(c0 + ty + j * 8) * HW + s0 + tx];
    __syncthreads();
    __half* ob = g_Xt + (size_t)bt * HW * CDIM;
    #pragma unroll
    for (int j = 0; j < 4; j++)
        ob[(size_t)(s0 + ty + j * 8) * CDIM + c0 + tx] = __float2half_rn(t[tx][ty + j * 8]);
}

// =====================================================================
// Pre-pass B: convert w_qkv fp32 -> fp16.
// =====================================================================
__global__ __launch_bounds__(256) void wcvt_kernel(const float* __restrict__ w_qkv)
{
    int i = blockIdx.x * 256 + threadIdx.x;
    float4 v = ((const float4*)w_qkv)[i];
    uint2 o;
    o.x = pack_h2(v.x, v.y);
    o.y = pack_h2(v.z, v.w);
    ((uint2*)g_Wq16)[i] = o;
}

// =====================================================================
// Kernel 1: Q/K/V projections, pure-fp16 pipeline. Per-scene.
// grid: (8, 4, 158), block 256
// =====================================================================
__global__ __launch_bounds__(256) void proj_gemm_kernel(
    const float* __restrict__ b_qkv, int scene)
{
    __shared__ __half Xs[128][40];
    __shared__ __half Ws[64][40];

    const int job = blockIdx.z;
    const __half* Xsrc; const __half* W16; const float* bias; __half* Out;
    float osc = 1.f;
    int tmode = 0;
    if (job < NVIEWS) {
        int i = job, bt = scene * NVIEWS + i, m = c_mha[i];
        W16  = g_Wq16 + (size_t)m * 3 * 65536;
        bias = b_qkv + m * 768;
        Xsrc = g_Xt + (size_t)bt * HW * CDIM;
        Out  = g_Qh + (size_t)bt * HW * CDIM;
        osc  = 0.17677669529663687f * 1.4426950408889634f;   // 1/sqrt(32)*log2(e)
    } else {
        int r    = job - NVIEWS;
        int kv   = r / NSLOT;
        int slot = r % NSLOT;
        int m    = c_pair_m[slot], src = c_pair_src[slot];
        W16  = g_Wq16 + (size_t)m * 3 * 65536 + (size_t)(1 + kv) * 65536;
        bias = b_qkv + m * 768 + (1 + kv) * 256;
        Xsrc = g_Xt + (size_t)(scene * NVIEWS + src) * HW * CDIM;
        if (kv == 0) {
            Out = g_Kh + (size_t)(scene * NSLOT + slot) * HW * CDIM;
        } else {
            Out = g_Vt + (size_t)(scene * NSLOT + slot) * CDIM * HW;
            tmode = 1;
        }
    }

    const int m0  = blockIdx.x * 128;
    const int c0f = blockIdx.y * 64;
    const __half* A = Xsrc + (size_t)m0 * CDIM;
    const __half* W = W16 + (size_t)c0f * CDIM;

    const int tid  = threadIdx.x;
    const int lane = tid & 31, warp = tid >> 5;
    const int g4   = lane >> 2, c4 = lane & 3;
    const int wm   = warp >> 1, wn = warp & 1;
    const int mw   = wm * 32, nw = wn * 32;

    float acc[2][4][4];
    #pragma unroll
    for (int mt = 0; mt < 2; mt++)
        #pragma unroll
        for (int nt = 0; nt < 4; nt++)
            #pragma unroll
            for (int j = 0; j < 4; j++) acc[mt][nt][j] = 0.f;

    for (int k0 = 0; k0 < CDIM; k0 += 32) {
        __syncthreads();
        #pragma unroll
        for (int l = 0; l < 2; l++) {
            int idx = tid + l * 256;
            int ss = idx >> 2, kc = idx & 3;
            *(uint4*)&Xs[ss][kc * 8] =
                *(const uint4*)(A + (size_t)ss * CDIM + k0 + kc * 8);
        }
        {
            int nn = tid >> 2, kc = tid & 3;
            *(uint4*)&Ws[nn][kc * 8] =
                *(const uint4*)(W + (size_t)nn * CDIM + k0 + kc * 8);
        }
        __syncthreads();

        #pragma unroll
        for (int kt = 0; kt < 2; kt++) {
            const int kk = kt * 16;
            uint32_t ah[2][4];
            #pragma unroll
            for (int mt = 0; mt < 2; mt++) {
                int mloc = mw + mt * 16;
                ah[mt][0] = *(const uint32_t*)&Xs[mloc + g4    ][kk + 2 * c4    ];
                ah[mt][1] = *(const uint32_t*)&Xs[mloc + g4 + 8][kk + 2 * c4    ];
                ah[mt][2] = *(const uint32_t*)&Xs[mloc + g4    ][kk + 2 * c4 + 8];
                ah[mt][3] = *(const uint32_t*)&Xs[mloc + g4 + 8][kk + 2 * c4 + 8];
            }
            uint32_t bh[4][2];
            #pragma unroll
            for (int nt = 0; nt < 4; nt++) {
                int nrow = nw + nt * 8 + g4;
                bh[nt][0] = *(const uint32_t*)&Ws[nrow][kk + 2 * c4    ];
                bh[nt][1] = *(const uint32_t*)&Ws[nrow][kk + 2 * c4 + 8];
            }
            #pragma unroll
            for (int mt = 0; mt < 2; mt++)
                #pragma unroll
                for (int nt = 0; nt < 4; nt++)
                    mma_fp16(acc[mt][nt], ah[mt][0], ah[mt][1], ah[mt][2], ah[mt][3],
                             bh[nt][0], bh[nt][1]);
        }
    }

    #pragma unroll
    for (int mt = 0; mt < 2; mt++) {
        int r = m0 + mw + mt * 16 + g4;
        #pragma unroll
        for (int nt = 0; nt < 4; nt++) {
            int c = c0f + nw + nt * 8 + 2 * c4;
            float2 bb = *(const float2*)(bias + nw + nt * 8 + 2 * c4);
            if (tmode == 0) {
                uint32_t o0 = pack_h2((acc[mt][nt][0] + bb.x) * osc,
                                      (acc[mt][nt][1] + bb.y) * osc);
                uint32_t o1 = pack_h2((acc[mt][nt][2] + bb.x) * osc,
                                      (acc[mt][nt][3] + bb.y) * osc);
                *(uint32_t*)(Out + (size_t)r       * CDIM + c) = o0;
                *(uint32_t*)(Out + (size_t)(r + 8) * CDIM + c) = o1;
            } else {
                Out[(size_t)c       * HW + r    ] = __float2half_rn(acc[mt][nt][0] + bb.x);
                Out[(size_t)(c + 1) * HW + r    ] = __float2half_rn(acc[mt][nt][1] + bb.y);
                Out[(size_t)c       * HW + r + 8] = __float2half_rn(acc[mt][nt][2] + bb.x);
                Out[(size_t)(c + 1) * HW + r + 8] = __float2half_rn(acc[mt][nt][3] + bb.y);
            }
        }
    }
}

// =====================================================================
// Kernel 2: fp16 flash attention (R13 tile shape: 32q/warp, 256q/CTA)
// with DOUBLE-BUFFERED smem K/V: one __syncthreads per tile (was 2),
// next tile's STS overlaps current tile's compute.
// Interleaved exp->PV groups; register prefetch of next K/V tile.
// grid: (4, 8, 26), block 256
// =====================================================================
__global__ __launch_bounds__(256) void attn_tc_kernel(int scene)
{
    __shared__ __half Ks[2][64][40];   // [buf][key][d]
    __shared__ __half Vs[2][32][72];   // [buf][d][key]

    const int tid  = threadIdx.x, lane = tid & 31, warp = tid >> 5;
    const int i    = blockIdx.z;
    const int b    = scene;
    const int bt   = scene * NVIEWS + i;
    const int h    = blockIdx.y;
    const int q0   = blockIdx.x * 256 + warp * 32;
    const int g4   = lane >> 2;
    const int c4   = lane & 3;

    // fill-role indices
    const int kr_row = tid >> 2, kr_q = tid & 3;   // K: 64 rows x 4 quads
    const int vr_d   = tid >> 3, vr_k = tid & 7;   // V: 32 rows x 8 quads

    // ---- Q fragments ----
    uint32_t qa[2][2][4];
    {
        const __half* Q = g_Qh + (size_t)bt * HW * CDIM + h * DHEAD;
        #pragma unroll
        for (int mt = 0; mt < 2; mt++)
            #pragma unroll
            for (int kt = 0; kt < 2; kt++) {
                int r = q0 + mt * 16 + g4;
                int c = kt * 16 + 2 * c4;
                qa[mt][kt][0] = *(const uint32_t*)(Q + (size_t)r       * CDIM + c);
                qa[mt][kt][1] = *(const uint32_t*)(Q + (size_t)(r + 8) * CDIM + c);
                qa[mt][kt][2] = *(const uint32_t*)(Q + (size_t)r       * CDIM + c + 8);
                qa[mt][kt][3] = *(const uint32_t*)(Q + (size_t)(r + 8) * CDIM + c + 8);
            }
    }

    float O[2][4][4];
    #pragma unroll
    for (int mt = 0; mt < 2; mt++)
        #pragma unroll
        for (int nd = 0; nd < 4; nd++)
            #pragma unroll
            for (int j = 0; j < 4; j++) O[mt][nd][j] = 0.f;
    float lsum[4] = {0.f, 0.f, 0.f, 0.f};   // [mt*2 + half]

    const int cnt   = c_selcnt[i];
    const int total = cnt * 16;              // 64-key tiles

    // ---- prefetch + store tile 0 into buffer 0 ----
    {
        int slot = c_slots[i][0];
        const __half* Kb = g_Kh + (size_t)(b * NSLOT + slot) * HW * CDIM + h * DHEAD;
        const __half* Vb = g_Vt + ((size_t)(b * NSLOT + slot) * CDIM + h * DHEAD) * HW;
        uint4 k0 = *(const uint4*)(Kb + (size_t)kr_row * CDIM + kr_q * 8);
        uint4 v0 = *(const uint4*)(Vb + (size_t)vr_d * HW + vr_k * 8);
        *(uint4*)&Ks[0][kr_row][kr_q * 8] = k0;
        *(uint4*)&Vs[0][vr_d][vr_k * 8]   = v0;
    }
    __syncthreads();

    for (int tile = 0; tile < total; tile++) {
        const int cur = tile & 1;
        const bool more = (tile + 1 < total);

        // issue next tile's loads early (consumed by STS after compute)
        uint4 pk, pv;
        if (more) {
            int nslot = c_slots[i][(tile + 1) >> 4];
            int nt0   = ((tile + 1) & 15) * 64;
            const __half* Kb = g_Kh + (size_t)(b * NSLOT + nslot) * HW * CDIM + h * DHEAD;
            const __half* Vb = g_Vt + ((size_t)(b * NSLOT + nslot) * CDIM + h * DHEAD) * HW;
            pk = *(const uint4*)(Kb + (size_t)(nt0 + kr_row) * CDIM + kr_q * 8);
            pv = *(const uint4*)(Vb + (size_t)vr_d * HW + nt0 + vr_k * 8);
        }

        #pragma unroll
        for (int half = 0; half < 2; half++) {
            // ---- QK for keys [half*32, half*32+32) ----
            float sc[2][4][4];
            #pragma unroll
            for (int mt = 0; mt < 2; mt++)
                #pragma unroll
                for (int n4 = 0; n4 < 4; n4++)
                    #pragma unroll
                    for (int j = 0; j < 4; j++) sc[mt][n4][j] = 0.f;

            #pragma unroll
            for (int n4 = 0; n4 < 4; n4++) {
                const __half* kr = &Ks[cur][(half * 4 + n4) * 8 + g4][0];
                #pragma unroll
                for (int kt = 0; kt < 2; kt++) {
                    uint32_t b0 = *(const uint32_t*)(kr + kt * 16 + 2 * c4);
                    uint32_t b1 = *(const uint32_t*)(kr + kt * 16 + 2 * c4 + 8);
                    mma_fp16(sc[0][n4], qa[0][kt][0], qa[0][kt][1], qa[0][kt][2], qa[0][kt][3], b0, b1);
                    mma_fp16(sc[1][n4], qa[1][kt][0], qa[1][kt][1], qa[1][kt][2], qa[1][kt][3], b0, b1);
                }
            }

            // ---- per 16-key group: exp -> PV (MUFU overlaps tensor) ----
            #pragma unroll
            for (int g = 0; g < 2; g++) {
                const int ko = half * 32 + g * 16;
                uint32_t pa0[4], pa1[4];
                {
                    float p00 = ex2f(sc[0][2*g][0]), p01 = ex2f(sc[0][2*g][1]);
                    float p02 = ex2f(sc[0][2*g][2]), p03 = ex2f(sc[0][2*g][3]);
                    float p10 = ex2f(sc[0][2*g+1][0]), p11 = ex2f(sc[0][2*g+1][1]);
                    float p12 = ex2f(sc[0][2*g+1][2]), p13 = ex2f(sc[0][2*g+1][3]);
                    lsum[0] += (p00 + p01) + (p10 + p11);
                    lsum[1] += (p02 + p03) + (p12 + p13);
                    pa0[0] = pack_h2(p00, p01);
                    pa0[1] = pack_h2(p02, p03);
                    pa0[2] = pack_h2(p10, p11);
                    pa0[3] = pack_h2(p12, p13);
                }
                {
                    float p00 = ex2f(sc[1][2*g][0]), p01 = ex2f(sc[1][2*g][1]);
                    float p02 = ex2f(sc[1][2*g][2]), p03 = ex2f(sc[1][2*g][3]);
                    float p10 = ex2f(sc[1][2*g+1][0]), p11 = ex2f(sc[1][2*g+1][1]);
                    float p12 = ex2f(sc[1][2*g+1][2]), p13 = ex2f(sc[1][2*g+1][3]);
                    lsum[2] += (p00 + p01) + (p10 + p11);
                    lsum[3] += (p02 + p03) + (p12 + p13);
                    pa1[0] = pack_h2(p00, p01);
                    pa1[1] = pack_h2(p02, p03);
                    pa1[2] = pack_h2(p10, p11);
                    pa1[3] = pack_h2(p12, p13);
                }
                #pragma unroll
                for (int nd = 0; nd < 4; nd++) {
                    const __half* vr = &Vs[cur][nd * 8 + g4][0];
                    uint32_t b0 = *(const uint32_t*)(vr + ko + 2 * c4);
                    uint32_t b1 = *(const uint32_t*)(vr + ko + 2 * c4 + 8);
                    mma_fp16(O[0][nd], pa0[0], pa0[1], pa0[2], pa0[3], b0, b1);
                    mma_fp16(O[1][nd], pa1[0], pa1[1], pa1[2], pa1[3], b0, b1);
                }
            }
        }

        // ---- store next tile into the other buffer, single barrier ----
        if (more) {
            *(uint4*)&Ks[cur ^ 1][kr_row][kr_q * 8] = pk;
            *(uint4*)&Vs[cur ^ 1][vr_d][vr_k * 8]   = pv;
            __syncthreads();
        }
    }

    // ---- finalize ----
    #pragma unroll
    for (int j = 0; j < 4; j++) {
        lsum[j] += __shfl_xor_sync(0xffffffffu, lsum[j], 1);
        lsum[j] += __shfl_xor_sync(0xffffffffu, lsum[j], 2);
        lsum[j] = 1.f / lsum[j];
    }

    float* Ob = g_AttO + (size_t)bt * HW * CDIM + h * DHEAD;
    #pragma unroll
    for (int mt = 0; mt < 2; mt++) {
        int r = q0 + mt * 16 + g4;
        #pragma unroll
        for (int nd = 0; nd < 4; nd++) {
            int col = nd * 8 + 2 * c4;
            float2 w0, w1;
            w0.x = O[mt][nd][0] * lsum[mt * 2 + 0];
            w0.y = O[mt][nd][1] * lsum[mt * 2 + 0];
            w1.x = O[mt][nd][2] * lsum[mt * 2 + 1];
            w1.y = O[mt][nd][3] * lsum[mt * 2 + 1];
            *(float2*)(Ob + (size_t)r       * CDIM + col) = w0;
            *(float2*)(Ob + (size_t)(r + 8) * CDIM + col) = w1;
        }
    }
}

// =====================================================================
// Kernel 3: output projection via split-fp16 MMA (3 products). Per-scene.
// grid: (8, 4, 26), block 256
// =====================================================================
struct SmemOut {
    __half Xh[128][40];
    __half Wh[64][40];
    __half Xl[128][40];
    __half Wl[64][40];
};

__global__ __launch_bounds__(256) void outproj_kernel(
    const float* __restrict__ w_out,
    const float* __restrict__ b_out,
    float* __restrict__ out, int scene)
{
    __shared__ SmemOut S;
    const int i  = blockIdx.z;
    const int bt = scene * NVIEWS + i;
    const int m  = c_mha[i];
    const float* W    = w_out + (size_t)m * 65536 + (size_t)(blockIdx.y * 64) * CDIM;
    const float* bias = b_out + m * 256 + blockIdx.y * 64;
    const float* A    = g_AttO + (size_t)bt * HW * CDIM + (size_t)(blockIdx.x * 128) * CDIM;
    float*       Op   = out + (size_t)bt * CDIM * HW;

    const int m0  = blockIdx.x * 128;
    const int c0f = blockIdx.y * 64;

    const int tid  = threadIdx.x;
    const int lane = tid & 31, warp = tid >> 5;
    const int g4   = lane >> 2, c4 = lane & 3;
    const int wm   = warp >> 1, wn = warp & 1;
    const int mw   = wm * 32, nw = wn * 32;

    float acc[2][4][4];
    #pragma unroll
    for (int mt = 0; mt < 2; mt++)
        #pragma unroll
        for (int nt = 0; nt < 4; nt++)
            #pragma unroll
            for (int j = 0; j < 4; j++) acc[mt][nt][j] = 0.f;

    for (int k0 = 0; k0 < CDIM; k0 += 32) {
        __syncthreads();
        #pragma unroll
        for (int l = 0; l < 4; l++) {
            int idx = tid + l * 256;
            int ss = idx >> 3, kc = idx & 7;
            float4 v = *(const float4*)(A + (size_t)ss * CDIM + k0 + kc * 4);
            __half h0,l0,h1,l1,h2,l2,h3,l3;
            f16_split(v.x, h0, l0); f16_split(v.y, h1, l1);
            f16_split(v.z, h2, l2); f16_split(v.w, h3, l3);
            __half2 ha; ha.x = h0; ha.y = h1;
            __half2 hb; hb.x = h2; hb.y = h3;
            __half2 la; la.x = l0; la.y = l1;
            __half2 lb; lb.x = l2; lb.y = l3;
            *(__half2*)&S.Xh[ss][kc * 4]     = ha;
            *(__half2*)&S.Xh[ss][kc * 4 + 2] = hb;
            *(__half2*)&S.Xl[ss][kc * 4]     = la;
            *(__half2*)&S.Xl[ss][kc * 4 + 2] = lb;
        }
        #pragma unroll
        for (int l = 0; l < 2; l++) {
            int idx = tid + l * 256;
            int nn = idx >> 3, kc = idx & 7;
            float4 v = *(const float4*)(W + (size_t)nn * CDIM + k0 + kc * 4);
            __half h0,l0,h1,l1,h2,l2,h3,l3;
            f16_split(v.x, h0, l0); f16_split(v.y, h1, l1);
            f16_split(v.z, h2, l2); f16_split(v.w, h3, l3);
            __half2 ha; ha.x = h0; ha.y = h1;
            __half2 hb; hb.x = h2; hb.y = h3;
            __half2 la; la.x = l0; la.y = l1;
            __half2 lb; lb.x = l2; lb.y = l3;
            *(__half2*)&S.Wh[nn][kc * 4]     = ha;
            *(__half2*)&S.Wh[nn][kc * 4 + 2] = hb;
            *(__half2*)&S.Wl[nn][kc * 4]     = la;
            *(__half2*)&S.Wl[nn][kc * 4 + 2] = lb;
        }
        __syncthreads();

        #pragma unroll
        for (int kt = 0; kt < 2; kt++) {
            const int kk = kt * 16;
            uint32_t ah[2][4], al[2][4];
            #pragma unroll
            for (int mt = 0; mt < 2; mt++) {
                int mloc = mw + mt * 16;
                ah[mt][0] = *(const uint32_t*)&S.Xh[mloc + g4    ][kk + 2 * c4    ];
                ah[mt][1] = *(const uint32_t*)&S.Xh[mloc + g4 + 8][kk + 2 * c4    ];
                ah[mt][2] = *(const uint32_t*)&S.Xh[mloc + g4    ][kk + 2 * c4 + 8];
                ah[mt][3] = *(const uint32_t*)&S.Xh[mloc + g4 + 8][kk + 2 * c4 + 8];
                al[mt][0] = *(const uint32_t*)&S.Xl[mloc + g4    ][kk + 2 * c4    ];
                al[mt][1] = *(const uint32_t*)&S.Xl[mloc + g4 + 8][kk + 2 * c4    ];
                al[mt][2] = *(const uint32_t*)&S.Xl[mloc + g4    ][kk + 2 * c4 + 8];
                al[mt][3] = *(const uint32_t*)&S.Xl[mloc + g4 + 8][kk + 2 * c4 + 8];
            }
            uint32_t bh[4][2], bl[4][2];
            #pragma unroll
            for (int nt = 0; nt < 4; nt++) {
                int nrow = nw + nt * 8 + g4;
                bh[nt][0] = *(const uint32_t*)&S.Wh[nrow][kk + 2 * c4    ];
                bh[nt][1] = *(const uint32_t*)&S.Wh[nrow][kk + 2 * c4 + 8];
                bl[nt][0] = *(const uint32_t*)&S.Wl[nrow][kk + 2 * c4    ];
                bl[nt][1] = *(const uint32_t*)&S.Wl[nrow][kk + 2 * c4 + 8];
            }
            #pragma unroll
            for (int mt = 0; mt < 2; mt++)
                #pragma unroll
                for (int nt = 0; nt < 4; nt++) {
                    mma_fp16(acc[mt][nt], ah[mt][0], ah[mt][1], ah[mt][2], ah[mt][3],
                             bh[nt][0], bh[nt][1]);
                    mma_fp16(acc[mt][nt], al[mt][0], al[mt][1], al[mt][2], al[mt][3],
                             bh[nt][0], bh[nt][1]);
                    mma_fp16(acc[mt][nt], ah[mt][0], ah[mt][1], ah[mt][2], ah[mt][3],
                             bl[nt][0], bl[nt][1]);
                }
        }
    }

    #pragma unroll
    for (int mt = 0; mt < 2; mt++) {
        int r = m0 + mw + mt * 16 + g4;
        #pragma unroll
        for (int nt = 0; nt < 4; nt++) {
            int c = c0f + nw + nt * 8 + 2 * c4;
            float2 bb = *(const float2*)(bias + nw + nt * 8 + 2 * c4);
            Op[(size_t)c       * HW + r    ] = acc[mt][nt][0] + bb.x;
            Op[(size_t)(c + 1) * HW + r    ] = acc[mt][nt][1] + bb.y;
            Op[(size_t)c       * HW + r + 8] = acc[mt][nt][2] + bb.x;
            Op[(size_t)(c + 1) * HW + r + 8] = acc[mt][nt][3] + bb.y;
        }
    }
}

// =====================================================================
// Launcher: two-scene fork/join on non-blocking streams (committed R12).
// =====================================================================
extern "C" void kernel_launch(void* const* d_in, const int* in_sizes, int n_in,
                              void* d_out, int out_size)
{
    const float* x     = (const float*)d_in[0];
    const float* w_qkv = (const float*)d_in[1];
    const float* b_qkv = (const float*)d_in[2];
    const float* w_out = (const float*)d_in[3];
    const float* b_out = (const float*)d_in[4];
    float* out = (float*)d_out;

    cudaStream_t sA, sB;
    cudaStreamCreateWithFlags(&sA, cudaStreamNonBlocking);
    cudaStreamCreateWithFlags(&sB, cudaStreamNonBlocking);
    cudaEvent_t eFork, eW, eA, eB;
    cudaEventCreateWithFlags(&eFork, cudaEventDisableTiming);
    cudaEventCreateWithFlags(&eW,    cudaEventDisableTiming);
    cudaEventCreateWithFlags(&eA,    cudaEventDisableTiming);
    cudaEventCreateWithFlags(&eB,    cudaEventDisableTiming);

    cudaEventRecord(eFork, 0);
    cudaStreamWaitEvent(sA, eFork, 0);
    cudaStreamWaitEvent(sB, eFork, 0);

    dim3 gx(HW / 32, CDIM / 32, NVIEWS);               // (32, 8, 26)
    dim3 g1(HW / 128, CDIM / 64, NVIEWS + 2 * NSLOT);  // (8, 4, 158)
    dim3 g2(HW / 256, NHEAD, NVIEWS);                  // (4, 8, 26)
    dim3 g3(HW / 128, CDIM / 64, NVIEWS);              // (8, 4, 26)

    wcvt_kernel<<<960, 256, 0, sA>>>(w_qkv);
    cudaEventRecord(eW, sA);
    xcvt_kernel<<<gx, 256, 0, sA>>>(x, 0);
    proj_gemm_kernel<<<g1, 256, 0, sA>>>(b_qkv, 0);
    attn_tc_kernel<<<g2, 256, 0, sA>>>(0);
    outproj_kernel<<<g3, 256, 0, sA>>>(w_out, b_out, out, 0);

    xcvt_kernel<<<gx, 256, 0, sB>>>(x, 1);
    cudaStreamWaitEvent(sB, eW, 0);
    proj_gemm_kernel<<<g1, 256, 0, sB>>>(b_qkv, 1);
    attn_tc_kernel<<<g2, 256, 0, sB>>>(1);
    outproj_kernel<<<g3, 256, 0, sB>>>(w_out, b_out, out, 1);

    cudaEventRecord(eA, sA);
    cudaEventRecord(eB, sB);
    cudaStreamWaitEvent(0, eA, 0);
    cudaStreamWaitEvent(0, eB, 0);

    cudaEventDestroy(eFork);
    cudaEventDestroy(eW);
    cudaEventDestroy(eA);
    cudaEventDestroy(eB);
    cudaStreamDestroy(sA);
    cudaStreamDestroy(sB);
}

// round 17
// speedup vs baseline: 1.1615x; 1.0750x over previous
#include <cuda_runtime.h>
#include <cuda_fp16.h>
#include <stdint.h>
#include <math.h>

#define NVIEWS 26
#define CDIM   256
#define HW     1024
#define NSLOT  66
#define NHEAD  8
#define DHEAD  32
#define NBT    52   // 2 scenes * 26 views

// ---------------- scratch (static device globals; no allocation) ----------------
__device__ __half g_Xt  [(size_t)NBT     * HW * CDIM];   // fp16 [bt][s][c]
__device__ __half g_Wq16[(size_t)5 * 3 * 65536];         // fp16 w_qkv
__device__ __half g_Qh  [(size_t)NBT     * HW * CDIM];   // fp16 [bt][s][c], pre-scaled
__device__ __half g_Kh  [(size_t)2*NSLOT * HW * CDIM];   // fp16 [slot][key][c]
__device__ __half g_Vt  [(size_t)2*NSLOT * CDIM * HW];   // fp16 [slot][d][key]
__device__ float  g_AttO[(size_t)NBT     * HW * CDIM];   // fp32 [bt][s][c]

// ---------------- precomputed graph tables ----------------
__constant__ int c_mha[26] = {0,1,2,2,2,2,2,2,2,2,3,3,3,3,3,3,3,3,4,4,4,4,4,4,4,4};

__constant__ int c_pair_m[66] = {
  0,0,0,0, 1,1,1,1,
  2,2,2,2,2,2,2,2,2,2,2,2,2,2,2,2,2,
  3,3,3,3,3,3,3,3,3,3,3,3,3,3,3,3,3,3,3,3,3,3,3,3,
  4,4,4,4,4,4,4,4,4,4,4,4,4,4,4,4,4
};
__constant__ int c_pair_src[66] = {
  18,20,22,24, 2,4,6,8,
  1,2,3,4,5,6,7,8,9,10,11,12,13,14,15,16,17,
  2,3,4,5,6,7,8,9,10,11,12,13,14,15,16,17,18,19,20,21,22,23,24,25,
  0,10,11,12,13,14,15,16,17,18,19,20,21,22,23,24,25
};

__constant__ int c_selcnt[26] = {4,4, 4,3,4,3,4,3,4,3, 4,4,4,4,4,4,4,4, 4,3,4,3,4,3,4,3};
__constant__ int c_slots[26][4] = {
  { 0, 1, 2, 3}, { 4, 5, 6, 7},
  { 8,10,16,17}, { 9,11,18,-1}, { 8,10,12,19}, {11,13,20,-1},
  { 8,12,14,21}, {13,15,22,-1}, { 8,14,16,23}, { 9,15,24,-1},
  {25,34,40,41}, {26,33,35,42}, {27,34,36,43}, {28,35,37,44},
  {29,36,38,45}, {30,37,39,46}, {31,38,40,47}, {32,33,39,48},
  {49,50,59,65}, {51,58,60,-1}, {49,52,59,61}, {53,60,62,-1},
  {49,54,61,63}, {55,62,64,-1}, {49,56,63,65}, {57,58,64,-1}
};

// ---------------- PTX helpers (compute_103-safe; sm_80+ features only) ----------------
__device__ __forceinline__ void mma_fp16(float* d,
    uint32_t a0, uint32_t a1, uint32_t a2, uint32_t a3,
    uint32_t b0, uint32_t b1)
{
    asm volatile(
        "mma.sync.aligned.m16n8k16.row.col.f32.f16.f16.f32 "
        "{%0,%1,%2,%3},{%4,%5,%6,%7},{%8,%9},{%0,%1,%2,%3};"
        : "+f"(d[0]), "+f"(d[1]), "+f"(d[2]), "+f"(d[3])
        : "r"(a0), "r"(a1), "r"(a2), "r"(a3), "r"(b0), "r"(b1));
}
__device__ __forceinline__ uint32_t pack_h2(float lo, float hi) {
    __half2 h = __floats2half2_rn(lo, hi);
    return *(uint32_t*)&h;
}
// 2^x on packed half2 via a single MUFU op (sm_75+; halves MUFU count)
__device__ __forceinline__ uint32_t ex2_h2(uint32_t x) {
    uint32_t y;
    asm("ex2.approx.f16x2 %0,%1;" : "=r"(y) : "r"(x));
    return y;
}
__device__ __forceinline__ void f16_split(float x, __half& h, __half& l) {
    h = __float2half_rn(x);
    l = __float2half_rn(x - __half2float(h));
}

// =====================================================================
// Pre-pass A: transpose+convert x [bt][c][s] fp32 -> g_Xt [bt][s][c] fp16.
// Per-scene: grid (32, 8, 26)
// =====================================================================
__global__ __launch_bounds__(256) void xcvt_kernel(const float* __restrict__ x, int scene)
{
    __shared__ float t[32][33];
    const int bt = scene * NVIEWS + blockIdx.z;
    const int s0 = blockIdx.x * 32, c0 = blockIdx.y * 32;
    const int tx = threadIdx.x & 31, ty = threadIdx.x >> 5;
    const float* xb = x + (size_t)bt * CDIM * HW;
    #pragma unroll
    for (int j = 0; j < 4; j++)
        t[ty + j * 8][tx] = xb[(size_t)(c0 + ty + j * 8) * HW + s0 + tx];
    __syncthreads();
    __half* ob = g_Xt + (size_t)bt * HW * CDIM;
    #pragma unroll
    for (int j = 0; j < 4; j++)
        ob[(size_t)(s0 + ty + j * 8) * CDIM + c0 + tx] = __float2half_rn(t[tx][ty + j * 8]);
}

// =====================================================================
// Pre-pass B: convert w_qkv fp32 -> fp16.
// =====================================================================
__global__ __launch_bounds__(256) void wcvt_kernel(const float* __restrict__ w_qkv)
{
    int i = blockIdx.x * 256 + threadIdx.x;
    float4 v = ((const float4*)w_qkv)[i];
    uint2 o;
    o.x = pack_h2(v.x, v.y);
    o.y = pack_h2(v.z, v.w);
    ((uint2*)g_Wq16)[i] = o;
}

// =====================================================================
// Kernel 1: Q/K/V projections, pure-fp16 pipeline. Per-scene.
// grid: (8, 4, 158), block 256
// =====================================================================
__global__ __launch_bounds__(256) void proj_gemm_kernel(
    const float* __restrict__ b_qkv, int scene)
{
    __shared__ __half Xs[128][40];
    __shared__ __half Ws[64][40];

    const int job = blockIdx.z;
    const __half* Xsrc; const __half* W16; const float* bias; __half* Out;
    float osc = 1.f;
    int tmode = 0;
    if (job < NVIEWS) {
        int i = job, bt = scene * NVIEWS + i, m = c_mha[i];
        W16  = g_Wq16 + (size_t)m * 3 * 65536;
        bias = b_qkv + m * 768;
        Xsrc = g_Xt + (size_t)bt * HW * CDIM;
        Out  = g_Qh + (size_t)bt * HW * CDIM;
        osc  = 0.17677669529663687f * 1.4426950408889634f;   // 1/sqrt(32)*log2(e)
    } else {
        int r    = job - NVIEWS;
        int kv   = r / NSLOT;
        int slot = r % NSLOT;
        int m    = c_pair_m[slot], src = c_pair_src[slot];
        W16  = g_Wq16 + (size_t)m * 3 * 65536 + (size_t)(1 + kv) * 65536;
        bias = b_qkv + m * 768 + (1 + kv) * 256;
        Xsrc = g_Xt + (size_t)(scene * NVIEWS + src) * HW * CDIM;
        if (kv == 0) {
            Out = g_Kh + (size_t)(scene * NSLOT + slot) * HW * CDIM;
        } else {
            Out = g_Vt + (size_t)(scene * NSLOT + slot) * CDIM * HW;
            tmode = 1;
        }
    }

    const int m0  = blockIdx.x * 128;
    const int c0f = blockIdx.y * 64;
    const __half* A = Xsrc + (size_t)m0 * CDIM;
    const __half* W = W16 + (size_t)c0f * CDIM;

    const int tid  = threadIdx.x;
    const int lane = tid & 31, warp = tid >> 5;
    const int g4   = lane >> 2, c4 = lane & 3;
    const int wm   = warp >> 1, wn = warp & 1;
    const int mw   = wm * 32, nw = wn * 32;

    float acc[2][4][4];
    #pragma unroll
    for (int mt = 0; mt < 2; mt++)
        #pragma unroll
        for (int nt = 0; nt < 4; nt++)
            #pragma unroll
            for (int j = 0; j < 4; j++) acc[mt][nt][j] = 0.f;

    for (int k0 = 0; k0 < CDIM; k0 += 32) {
        __syncthreads();
        #pragma unroll
        for (int l = 0; l < 2; l++) {
            int idx = tid + l * 256;
            int ss = idx >> 2, kc = idx & 3;
            *(uint4*)&Xs[ss][kc * 8] =
                *(const uint4*)(A + (size_t)ss * CDIM + k0 + kc * 8);
        }
        {
            int nn = tid >> 2, kc = tid & 3;
            *(uint4*)&Ws[nn][kc * 8] =
                *(const uint4*)(W + (size_t)nn * CDIM + k0 + kc * 8);
        }
        __syncthreads();

        #pragma unroll
        for (int kt = 0; kt < 2; kt++) {
            const int kk = kt * 16;
            uint32_t ah[2][4];
            #pragma unroll
            for (int mt = 0; mt < 2; mt++) {
                int mloc = mw + mt * 16;
                ah[mt][0] = *(const uint32_t*)&Xs[mloc + g4    ][kk + 2 * c4    ];
                ah[mt][1] = *(const uint32_t*)&Xs[mloc + g4 + 8][kk + 2 * c4    ];
                ah[mt][2] = *(const uint32_t*)&Xs[mloc + g4    ][kk + 2 * c4 + 8];
                ah[mt][3] = *(const uint32_t*)&Xs[mloc + g4 + 8][kk + 2 * c4 + 8];
            }
            uint32_t bh[4][2];
            #pragma unroll
            for (int nt = 0; nt < 4; nt++) {
                int nrow = nw + nt * 8 + g4;
                bh[nt][0] = *(const uint32_t*)&Ws[nrow][kk + 2 * c4    ];
                bh[nt][1] = *(const uint32_t*)&Ws[nrow][kk + 2 * c4 + 8];
            }
            #pragma unroll
            for (int mt = 0; mt < 2; mt++)
                #pragma unroll
                for (int nt = 0; nt < 4; nt++)
                    mma_fp16(acc[mt][nt], ah[mt][0], ah[mt][1], ah[mt][2], ah[mt][3],
                             bh[nt][0], bh[nt][1]);
        }
    }

    #pragma unroll
    for (int mt = 0; mt < 2; mt++) {
        int r = m0 + mw + mt * 16 + g4;
        #pragma unroll
        for (int nt = 0; nt < 4; nt++) {
            int c = c0f + nw + nt * 8 + 2 * c4;
            float2 bb = *(const float2*)(bias + nw + nt * 8 + 2 * c4);
            if (tmode == 0) {
                uint32_t o0 = pack_h2((acc[mt][nt][0] + bb.x) * osc,
                                      (acc[mt][nt][1] + bb.y) * osc);
                uint32_t o1 = pack_h2((acc[mt][nt][2] + bb.x) * osc,
                                      (acc[mt][nt][3] + bb.y) * osc);
                *(uint32_t*)(Out + (size_t)r       * CDIM + c) = o0;
                *(uint32_t*)(Out + (size_t)(r + 8) * CDIM + c) = o1;
            } else {
                Out[(size_t)c       * HW + r    ] = __float2half_rn(acc[mt][nt][0] + bb.x);
                Out[(size_t)(c + 1) * HW + r    ] = __float2half_rn(acc[mt][nt][1] + bb.y);
                Out[(size_t)c       * HW + r + 8] = __float2half_rn(acc[mt][nt][2] + bb.x);
                Out[(size_t)(c + 1) * HW + r + 8] = __float2half_rn(acc[mt][nt][3] + bb.y);
            }
        }
    }
}

// =====================================================================
// Kernel 2: fp16 flash attention (R15 base: 32q/warp, double-buffered)
// + f16x2 exp (halves MUFU instr count: pack scores to half2 FIRST,
//   then one ex2.approx.f16x2 per pair)
// + ones-column lsum (R10-validated): V tile rows 32..39, extra PV nd.
//   Denominator = exact fp32 row-sum of the SAME fp16 P as numerator,
//   so common-mode P error cancels in the division.
// grid: (4, 8, 26), block 256
// =====================================================================
__global__ __launch_bounds__(256) void attn_tc_kernel(int scene)
{
    __shared__ __half Ks[2][64][40];   // [buf][key][d]
    __shared__ __half Vs[2][40][72];   // [buf][d][key]; rows 32..39 = ones block

    const int tid  = threadIdx.x, lane = tid & 31, warp = tid >> 5;
    const int i    = blockIdx.z;
    const int b    = scene;
    const int bt   = scene * NVIEWS + i;
    const int h    = blockIdx.y;
    const int q0   = blockIdx.x * 256 + warp * 32;
    const int g4   = lane >> 2;
    const int c4   = lane & 3;

    // fill-role indices
    const int kr_row = tid >> 2, kr_q = tid & 3;   // K: 64 rows x 4 quads
    const int vr_d   = tid >> 3, vr_k = tid & 7;   // V: 32 rows x 8 quads

    // ones-column block init (rows 32..39 of both buffers; persistent)
    for (int idx = tid; idx < 8 * 72; idx += 256) {
        int d = idx / 72, key = idx - d * 72;
        __half v = (d == 0) ? __float2half(1.f) : __float2half(0.f);
        Vs[0][32 + d][key] = v;
        Vs[1][32 + d][key] = v;
    }

    // ---- Q fragments ----
    uint32_t qa[2][2][4];
    {
        const __half* Q = g_Qh + (size_t)bt * HW * CDIM + h * DHEAD;
        #pragma unroll
        for (int mt = 0; mt < 2; mt++)
            #pragma unroll
            for (int kt = 0; kt < 2; kt++) {
                int r = q0 + mt * 16 + g4;
                int c = kt * 16 + 2 * c4;
                qa[mt][kt][0] = *(const uint32_t*)(Q + (size_t)r       * CDIM + c);
                qa[mt][kt][1] = *(const uint32_t*)(Q + (size_t)(r + 8) * CDIM + c);
                qa[mt][kt][2] = *(const uint32_t*)(Q + (size_t)r       * CDIM + c + 8);
                qa[mt][kt][3] = *(const uint32_t*)(Q + (size_t)(r + 8) * CDIM + c + 8);
            }
    }

    float O[2][5][4];   // nd=4 is the lsum (ones) tile
    #pragma unroll
    for (int mt = 0; mt < 2; mt++)
        #pragma unroll
        for (int nd = 0; nd < 5; nd++)
            #pragma unroll
            for (int j = 0; j < 4; j++) O[mt][nd][j] = 0.f;

    const int cnt   = c_selcnt[i];
    const int total = cnt * 16;              // 64-key tiles

    // ---- prefetch + store tile 0 into buffer 0 ----
    {
        int slot = c_slots[i][0];
        const __half* Kb = g_Kh + (size_t)(b * NSLOT + slot) * HW * CDIM + h * DHEAD;
        const __half* Vb = g_Vt + ((size_t)(b * NSLOT + slot) * CDIM + h * DHEAD) * HW;
        uint4 k0 = *(const uint4*)(Kb + (size_t)kr_row * CDIM + kr_q * 8);
        uint4 v0 = *(const uint4*)(Vb + (size_t)vr_d * HW + vr_k * 8);
        *(uint4*)&Ks[0][kr_row][kr_q * 8] = k0;
        *(uint4*)&Vs[0][vr_d][vr_k * 8]   = v0;
    }
    __syncthreads();

    for (int tile = 0; tile < total; tile++) {
        const int cur = tile & 1;
        const bool more = (tile + 1 < total);

        // issue next tile's loads early (consumed by STS after compute)
        uint4 pk, pv;
        if (more) {
            int nslot = c_slots[i][(tile + 1) >> 4];
            int nt0   = ((tile + 1) & 15) * 64;
            const __half* Kb = g_Kh + (size_t)(b * NSLOT + nslot) * HW * CDIM + h * DHEAD;
            const __half* Vb = g_Vt + ((size_t)(b * NSLOT + nslot) * CDIM + h * DHEAD) * HW;
            pk = *(const uint4*)(Kb + (size_t)(nt0 + kr_row) * CDIM + kr_q * 8);
            pv = *(const uint4*)(Vb + (size_t)vr_d * HW + nt0 + vr_k * 8);
        }

        #pragma unroll
        for (int half = 0; half < 2; half++) {
            // ---- QK for keys [half*32, half*32+32) ----
            float sc[2][4][4];
            #pragma unroll
            for (int mt = 0; mt < 2; mt++)
                #pragma unroll
                for (int n4 = 0; n4 < 4; n4++)
                    #pragma unroll
                    for (int j = 0; j < 4; j++) sc[mt][n4][j] = 0.f;

            #pragma unroll
            for (int n4 = 0; n4 < 4; n4++) {
                const __half* kr = &Ks[cur][(half * 4 + n4) * 8 + g4][0];
                #pragma unroll
                for (int kt = 0; kt < 2; kt++) {
                    uint32_t b0 = *(const uint32_t*)(kr + kt * 16 + 2 * c4);
                    uint32_t b1 = *(const uint32_t*)(kr + kt * 16 + 2 * c4 + 8);
                    mma_fp16(sc[0][n4], qa[0][kt][0], qa[0][kt][1], qa[0][kt][2], qa[0][kt][3], b0, b1);
                    mma_fp16(sc[1][n4], qa[1][kt][0], qa[1][kt][1], qa[1][kt][2], qa[1][kt][3], b0, b1);
                }
            }

            // ---- per 16-key group: pack->f16x2 exp->PV (half the MUFU ops) ----
            #pragma unroll
            for (int g = 0; g < 2; g++) {
                const int ko = half * 32 + g * 16;
                uint32_t pa0[4], pa1[4];
                pa0[0] = ex2_h2(pack_h2(sc[0][2*g][0],   sc[0][2*g][1]));
                pa0[1] = ex2_h2(pack_h2(sc[0][2*g][2],   sc[0][2*g][3]));
                pa0[2] = ex2_h2(pack_h2(sc[0][2*g+1][0], sc[0][2*g+1][1]));
                pa0[3] = ex2_h2(pack_h2(sc[0][2*g+1][2], sc[0][2*g+1][3]));
                pa1[0] = ex2_h2(pack_h2(sc[1][2*g][0],   sc[1][2*g][1]));
                pa1[1] = ex2_h2(pack_h2(sc[1][2*g][2],   sc[1][2*g][3]));
                pa1[2] = ex2_h2(pack_h2(sc[1][2*g+1][0], sc[1][2*g+1][1]));
                pa1[3] = ex2_h2(pack_h2(sc[1][2*g+1][2], sc[1][2*g+1][3]));
                #pragma unroll
                for (int nd = 0; nd < 5; nd++) {
                    const __half* vr = &Vs[cur][nd * 8 + g4][0];
                    uint32_t b0 = *(const uint32_t*)(vr + ko + 2 * c4);
                    uint32_t b1 = *(const uint32_t*)(vr + ko + 2 * c4 + 8);
                    mma_fp16(O[0][nd], pa0[0], pa0[1], pa0[2], pa0[3], b0, b1);
                    mma_fp16(O[1][nd], pa1[0], pa1[1], pa1[2], pa1[3], b0, b1);
                }
            }
        }

        // ---- store next tile into the other buffer, single barrier ----
        if (more) {
            *(uint4*)&Ks[cur ^ 1][kr_row][kr_q * 8] = pk;
            *(uint4*)&Vs[cur ^ 1][vr_d][vr_k * 8]   = pv;
            __syncthreads();
        }
    }

    // ---- finalize: lsum from the ones tile (col lives on lane c4==0) ----
    const int srcl = (lane >> 2) << 2;
    float* Ob = g_AttO + (size_t)bt * HW * CDIM + h * DHEAD;
    #pragma unroll
    for (int mt = 0; mt < 2; mt++) {
        float s0 = __shfl_sync(0xffffffffu, O[mt][4][0], srcl);
        float s1 = __shfl_sync(0xffffffffu, O[mt][4][2], srcl);
        float inv0 = 1.f / s0, inv1 = 1.f / s1;
        int r = q0 + mt * 16 + g4;
        #pragma unroll
        for (int nd = 0; nd < 4; nd++) {
            int col = nd * 8 + 2 * c4;
            float2 w0, w1;
            w0.x = O[mt][nd][0] * inv0;
            w0.y = O[mt][nd][1] * inv0;
            w1.x = O[mt][nd][2] * inv1;
            w1.y = O[mt][nd][3] * inv1;
            *(float2*)(Ob + (size_t)r       * CDIM + col) = w0;
            *(float2*)(Ob + (size_t)(r + 8) * CDIM + col) = w1;
        }
    }
}

// =====================================================================
// Kernel 3: output projection via split-fp16 MMA (3 products). Per-scene.
// grid: (8, 4, 26), block 256
// =====================================================================
struct SmemOut {
    __half Xh[128][40];
    __half Wh[64][40];
    __half Xl[128][40];
    __half Wl[64][40];
};

__global__ __launch_bounds__(256) void outproj_kernel(
    const float* __restrict__ w_out,
    const float* __restrict__ b_out,
    float* __restrict__ out, int scene)
{
    __shared__ SmemOut S;
    const int i  = blockIdx.z;
    const int bt = scene * NVIEWS + i;
    const int m  = c_mha[i];
    const float* W    = w_out + (size_t)m * 65536 + (size_t)(blockIdx.y * 64) * CDIM;
    const float* bias = b_out + m * 256 + blockIdx.y * 64;
    const float* A    = g_AttO + (size_t)bt * HW * CDIM + (size_t)(blockIdx.x * 128) * CDIM;
    float*       Op   = out + (size_t)bt * CDIM * HW;

    const int m0  = blockIdx.x * 128;
    const int c0f = blockIdx.y * 64;

    const int tid  = threadIdx.x;
    const int lane = tid & 31, warp = tid >> 5;
    const int g4   = lane >> 2, c4 = lane & 3;
    const int wm   = warp >> 1, wn = warp & 1;
    const int mw   = wm * 32, nw = wn * 32;

    float acc[2][4][4];
    #pragma unroll
    for (int mt = 0; mt < 2; mt++)
        #pragma unroll
        for (int nt = 0; nt < 4; nt++)
            #pragma unroll
            for (int j = 0; j < 4; j++) acc[mt][nt][j] = 0.f;

    for (int k0 = 0; k0 < CDIM; k0 += 32) {
        __syncthreads();
        #pragma unroll
        for (int l = 0; l < 4; l++) {
            int idx = tid + l * 256;
            int ss = idx >> 3, kc = idx & 7;
            float4 v = *(const float4*)(A + (size_t)ss * CDIM + k0 + kc * 4);
            __half h0,l0,h1,l1,h2,l2,h3,l3;
            f16_split(v.x, h0, l0); f16_split(v.y, h1, l1);
            f16_split(v.z, h2, l2); f16_split(v.w, h3, l3);
            __half2 ha; ha.x = h0; ha.y = h1;
            __half2 hb; hb.x = h2; hb.y = h3;
            __half2 la; la.x = l0; la.y = l1;
            __half2 lb; lb.x = l2; lb.y = l3;
            *(__half2*)&S.Xh[ss][kc * 4]     = ha;
            *(__half2*)&S.Xh[ss][kc * 4 + 2] = hb;
            *(__half2*)&S.Xl[ss][kc * 4]     = la;
            *(__half2*)&S.Xl[ss][kc * 4 + 2] = lb;
        }
        #pragma unroll
        for (int l = 0; l < 2; l++) {
            int idx = tid + l * 256;
            int nn = idx >> 3, kc = idx & 7;
            float4 v = *(const float4*)(W + (size_t)nn * CDIM + k0 + kc * 4);
            __half h0,l0,h1,l1,h2,l2,h3,l3;
            f16_split(v.x, h0, l0); f16_split(v.y, h1, l1);
            f16_split(v.z, h2, l2); f16_split(v.w, h3, l3);
            __half2 ha; ha.x = h0; ha.y = h1;
            __half2 hb; hb.x = h2; hb.y = h3;
            __half2 la; la.x = l0; la.y = l1;
            __half2 lb; lb.x = l2; lb.y = l3;
            *(__half2*)&S.Wh[nn][kc * 4]     = ha;
            *(__half2*)&S.Wh[nn][kc * 4 + 2] = hb;
            *(__half2*)&S.Wl[nn][kc * 4]     = la;
            *(__half2*)&S.Wl[nn][kc * 4 + 2] = lb;
        }
        __syncthreads();

        #pragma unroll
        for (int kt = 0; kt < 2; kt++) {
            const int kk = kt * 16;
            uint32_t ah[2][4], al[2][4];
            #pragma unroll
            for (int mt = 0; mt < 2; mt++) {
                int mloc = mw + mt * 16;
                ah[mt][0] = *(const uint32_t*)&S.Xh[mloc + g4    ][kk + 2 * c4    ];
                ah[mt][1] = *(const uint32_t*)&S.Xh[mloc + g4 + 8][kk + 2 * c4    ];
                ah[mt][2] = *(const uint32_t*)&S.Xh[mloc + g4    ][kk + 2 * c4 + 8];
                ah[mt][3] = *(const uint32_t*)&S.Xh[mloc + g4 + 8][kk + 2 * c4 + 8];
                al[mt][0] = *(const uint32_t*)&S.Xl[mloc + g4    ][kk + 2 * c4    ];
                al[mt][1] = *(const uint32_t*)&S.Xl[mloc + g4 + 8][kk + 2 * c4    ];
                al[mt][2] = *(const uint32_t*)&S.Xl[mloc + g4    ][kk + 2 * c4 + 8];
                al[mt][3] = *(const uint32_t*)&S.Xl[mloc + g4 + 8][kk + 2 * c4 + 8];
            }
            uint32_t bh[4][2], bl[4][2];
            #pragma unroll
            for (int nt = 0; nt < 4; nt++) {
                int nrow = nw + nt * 8 + g4;
                bh[nt][0] = *(const uint32_t*)&S.Wh[nrow][kk + 2 * c4    ];
                bh[nt][1] = *(const uint32_t*)&S.Wh[nrow][kk + 2 * c4 + 8];
                bl[nt][0] = *(const uint32_t*)&S.Wl[nrow][kk + 2 * c4    ];
                bl[nt][1] = *(const uint32_t*)&S.Wl[nrow][kk + 2 * c4 + 8];
            }
            #pragma unroll
            for (int mt = 0; mt < 2; mt++)
                #pragma unroll
                for (int nt = 0; nt < 4; nt++) {
                    mma_fp16(acc[mt][nt], ah[mt][0], ah[mt][1], ah[mt][2], ah[mt][3],
                             bh[nt][0], bh[nt][1]);
                    mma_fp16(acc[mt][nt], al[mt][0], al[mt][1], al[mt][2], al[mt][3],
                             bh[nt][0], bh[nt][1]);
                    mma_fp16(acc[mt][nt], ah[mt][0], ah[mt][1], ah[mt][2], ah[mt][3],
                             bl[nt][0], bl[nt][1]);
                }
        }
    }

    #pragma unroll
    for (int mt = 0; mt < 2; mt++) {
        int r = m0 + mw + mt * 16 + g4;
        #pragma unroll
        for (int nt = 0; nt < 4; nt++) {
            int c = c0f + nw + nt * 8 + 2 * c4;
            float2 bb = *(const float2*)(bias + nw + nt * 8 + 2 * c4);
            Op[(size_t)c       * HW + r    ] = acc[mt][nt][0] + bb.x;
            Op[(size_t)(c + 1) * HW + r    ] = acc[mt][nt][1] + bb.y;
            Op[(size_t)c       * HW + r + 8] = acc[mt][nt][2] + bb.x;
            Op[(size_t)(c + 1) * HW + r + 8] = acc[mt][nt][3] + bb.y;
        }
    }
}

// =====================================================================
// Launcher: two-scene fork/join on non-blocking streams (committed R12).
// =====================================================================
extern "C" void kernel_launch(void* const* d_in, const int* in_sizes, int n_in,
                              void* d_out, int out_size)
{
    const float* x     = (const float*)d_in[0];
    const float* w_qkv = (const float*)d_in[1];
    const float* b_qkv = (const float*)d_in[2];
    const float* w_out = (const float*)d_in[3];
    const float* b_out = (const float*)d_in[4];
    float* out = (float*)d_out;

    cudaStream_t sA, sB;
    cudaStreamCreateWithFlags(&sA, cudaStreamNonBlocking);
    cudaStreamCreateWithFlags(&sB, cudaStreamNonBlocking);
    cudaEvent_t eFork, eW, eA, eB;
    cudaEventCreateWithFlags(&eFork, cudaEventDisableTiming);
    cudaEventCreateWithFlags(&eW,    cudaEventDisableTiming);
    cudaEventCreateWithFlags(&eA,    cudaEventDisableTiming);
    cudaEventCreateWithFlags(&eB,    cudaEventDisableTiming);

    cudaEventRecord(eFork, 0);
    cudaStreamWaitEvent(sA, eFork, 0);
    cudaStreamWaitEvent(sB, eFork, 0);

    dim3 gx(HW / 32, CDIM / 32, NVIEWS);               // (32, 8, 26)
    dim3 g1(HW / 128, CDIM / 64, NVIEWS + 2 * NSLOT);  // (8, 4, 158)
    dim3 g2(HW / 256, NHEAD, NVIEWS);                  // (4, 8, 26)
    dim3 g3(HW / 128, CDIM / 64, NVIEWS);              // (8, 4, 26)

    wcvt_kernel<<<960, 256, 0, sA>>>(w_qkv);
    cudaEventRecord(eW, sA);
    xcvt_kernel<<<gx, 256, 0, sA>>>(x, 0);
    proj_gemm_kernel<<<g1, 256, 0, sA>>>(b_qkv, 0);
    attn_tc_kernel<<<g2, 256, 0, sA>>>(0);
    outproj_kernel<<<g3, 256, 0, sA>>>(w_out, b_out, out, 0);

    xcvt_kernel<<<gx, 256, 0, sB>>>(x, 1);
    cudaStreamWaitEvent(sB, eW, 0);
    proj_gemm_kernel<<<g1, 256, 0, sB>>>(b_qkv, 1);
    attn_tc_kernel<<<g2, 256, 0, sB>>>(1);
    outproj_kernel<<<g3, 256, 0, sB>>>(w_out, b_out, out, 1);

    cudaEventRecord(eA, sA);
    cudaEventRecord(eB, sB);
    cudaStreamWaitEvent(0, eA, 0);
    cudaStreamWaitEvent(0, eB, 0);

    cudaEventDestroy(eFork);
    cudaEventDestroy(eW);
    cudaEventDestroy(eA);
    cudaEventDestroy(eB);
    cudaStreamDestroy(sA);
    cudaStreamDestroy(sB);
}